// round 14
// baseline (speedup 1.0000x reference)
#include <cuda_runtime.h>
#include <cuda_bf16.h>

#define N 512
#define D 128
#define A 4
#define T 1024
#define RS 520
#define NPOS_MAX 64
#define MARGIN 1.0f
#define EPSF 1e-8f

typedef unsigned long long u64;

__device__ __forceinline__ u64 ffma2(u64 a, u64 b, u64 c) {
    u64 d;
    asm("fma.rn.f32x2 %0, %1, %2, %3;" : "=l"(d) : "l"(a), "l"(b), "l"(c));
    return d;
}
__device__ __forceinline__ float hsum2(u64 v) {
    float lo, hi;
    asm("mov.b64 {%0, %1}, %2;" : "=f"(lo), "=f"(hi) : "l"(v));
    return lo + hi;
}

__device__ double             g_sum;
__device__ unsigned long long g_cnt;
__device__ unsigned int       g_done;

__global__ __launch_bounds__(T, 1) void triplet_k(const float* __restrict__ E,
                                                  const int* __restrict__ lab,
                                                  float* __restrict__ out) {
    __shared__ float        s_ea[A * D];
    __shared__ float        s_row[A * RS];
    __shared__ float        s_prow[A * NPOS_MAX];
    __shared__ int          s_lab[N];
    __shared__ short        s_pos[A][NPOS_MAX];
    __shared__ int          s_np[A];
    __shared__ double       s_wsum[T / 32];
    __shared__ unsigned int s_wcnt[T / 32];
    __shared__ int          s_last;

    const int i0   = blockIdx.x * A;
    const int tid  = threadIdx.x;
    const int lane = tid & 31;
    const int w    = tid >> 5;            // 32 warps

    if (tid < A) s_np[tid] = 0;
    if (tid < A * D) s_ea[tid] = E[i0 * D + tid];
    if (tid < N)     s_lab[tid] = lab[tid];
    __syncthreads();

    // positives (threads 0..511, one j each)
    if (tid < N) {
        const int lj = s_lab[tid];
#pragma unroll
        for (int a = 0; a < A; a++) {
            if (tid != i0 + a && lj == s_lab[i0 + a]) {
                int p = atomicAdd(&s_np[a], 1);
                s_pos[a][p] = (short)tid;
            }
        }
    }
    __syncthreads();

    // ---- dot phase: warp w owns rows [16w,16w+16); 8-lane group per row-slot ----
    // lane = 8r+s; group g covers passes {2g, 2g+1} i.e. rows base+8g, base+8g+4
    {
        const int r = lane >> 3;
        const int s = lane & 7;
        const bool b1 = lane & 1;
        const bool b2 = lane & 2;
        const int base = (w << 4) + r;
        const float* ea = s_ea + s * 4;

#pragma unroll
        for (int g = 0; g < 2; g++) {
            const float* ejA = E + (base + 8 * g + 0) * D + s * 4;
            const float* ejB = E + (base + 8 * g + 4) * D + s * 4;

            u64 acc[2][4];   // [row-in-group][anchor], packed f32x2
#pragma unroll
            for (int t = 0; t < 2; t++)
#pragma unroll
                for (int a = 0; a < 4; a++) acc[t][a] = 0ULL;

#pragma unroll
            for (int q = 0; q < 4; q++) {
                const ulonglong2 a0 = *(const ulonglong2*)(ea + 0 * D + q * 32);
                const ulonglong2 a1 = *(const ulonglong2*)(ea + 1 * D + q * 32);
                const ulonglong2 a2 = *(const ulonglong2*)(ea + 2 * D + q * 32);
                const ulonglong2 a3 = *(const ulonglong2*)(ea + 3 * D + q * 32);
                const ulonglong2 vA = *(const ulonglong2*)(ejA + q * 32);
                const ulonglong2 vB = *(const ulonglong2*)(ejB + q * 32);

                acc[0][0] = ffma2(vA.x, a0.x, acc[0][0]);
                acc[0][0] = ffma2(vA.y, a0.y, acc[0][0]);
                acc[0][1] = ffma2(vA.x, a1.x, acc[0][1]);
                acc[0][1] = ffma2(vA.y, a1.y, acc[0][1]);
                acc[0][2] = ffma2(vA.x, a2.x, acc[0][2]);
                acc[0][2] = ffma2(vA.y, a2.y, acc[0][2]);
                acc[0][3] = ffma2(vA.x, a3.x, acc[0][3]);
                acc[0][3] = ffma2(vA.y, a3.y, acc[0][3]);

                acc[1][0] = ffma2(vB.x, a0.x, acc[1][0]);
                acc[1][0] = ffma2(vB.y, a0.y, acc[1][0]);
                acc[1][1] = ffma2(vB.x, a1.x, acc[1][1]);
                acc[1][1] = ffma2(vB.y, a1.y, acc[1][1]);
                acc[1][2] = ffma2(vB.x, a2.x, acc[1][2]);
                acc[1][2] = ffma2(vB.y, a2.y, acc[1][2]);
                acc[1][3] = ffma2(vB.x, a3.x, acc[1][3]);
                acc[1][3] = ffma2(vB.y, a3.y, acc[1][3]);
            }

            // reduce: per row-in-group, packed butterfly over 8-lane group
#pragma unroll
            for (int t = 0; t < 2; t++) {
                const float c0 = hsum2(acc[t][0]);
                const float c1 = hsum2(acc[t][1]);
                const float c2 = hsum2(acc[t][2]);
                const float c3 = hsum2(acc[t][3]);
                float p01 = (b1 ? c1 : c0) + __shfl_xor_sync(0xffffffffu, b1 ? c0 : c1, 1);
                float p23 = (b1 ? c3 : c2) + __shfl_xor_sync(0xffffffffu, b1 ? c2 : c3, 1);
                float qv  = (b2 ? p23 : p01) + __shfl_xor_sync(0xffffffffu, b2 ? p01 : p23, 2);
                qv += __shfl_xor_sync(0xffffffffu, qv, 4);
                if ((lane & 4) == 0)
                    s_row[(lane & 3) * RS + base + 8 * g + 4 * t] = qv;
            }
        }
    }
    __syncthreads();

    // ---- compact positive row values ----
    if (tid < A * NPOS_MAX) {
        const int a = tid >> 6;
        const int p = tid & 63;
        if (p < s_np[a]) s_prow[(a << 6) + p] = s_row[a * RS + s_pos[a][p]];
    }
    __syncthreads();

    // ---- hinge phase: thread owns k; half-split over positives ----
    float lsum = 0.f;
    unsigned int lcnt = 0;
    {
        const int k    = tid & (N - 1);
        const int h    = tid >> 9;
        const int labk = s_lab[k];
        const float tv[A] = { MARGIN - s_row[0 * RS + k], MARGIN - s_row[1 * RS + k],
                              MARGIN - s_row[2 * RS + k], MARGIN - s_row[3 * RS + k] };

#pragma unroll
        for (int a = 0; a < A; a++) {
            if (labk != s_lab[i0 + a]) {
                const int    np = s_np[a];
                const float  ta = tv[a];
                const float* pr = s_prow + (a << 6);
                for (int p = h; p < np; p += 2) {
                    const float v = pr[p] + ta;
                    if (v > 0.f)  lsum += v;
                    if (v > EPSF) lcnt++;
                }
            }
        }
    }

    // ---- block reduction ----
    double dsum = (double)lsum;
#pragma unroll
    for (int o = 16; o > 0; o >>= 1) {
        dsum += __shfl_down_sync(0xffffffffu, dsum, o);
        lcnt += __shfl_down_sync(0xffffffffu, lcnt, o);
    }
    if (lane == 0) { s_wsum[w] = dsum; s_wcnt[w] = lcnt; }
    __syncthreads();

    if (tid == 0) {
        double t = 0.0;
        unsigned int c = 0;
#pragma unroll
        for (int ww = 0; ww < T / 32; ww++) { t += s_wsum[ww]; c += s_wcnt[ww]; }
        if (t != 0.0 || c != 0) {
            atomicAdd(&g_sum, t);
            atomicAdd(&g_cnt, (unsigned long long)c);
        }
        __threadfence();
        const unsigned int d = atomicAdd(&g_done, 1u);
        s_last = (d == gridDim.x - 1);
    }
    __syncthreads();

    if (s_last && tid == 0) {
        const double             s = atomicAdd(&g_sum, 0.0);
        const unsigned long long c = atomicAdd(&g_cnt, 0ULL);
        out[0] = (float)(s / ((double)c + (double)EPSF));
        g_sum  = 0.0;
        g_cnt  = 0ULL;
        atomicExch(&g_done, 0u);
    }
}

extern "C" void kernel_launch(void* const* d_in, const int* in_sizes, int n_in,
                              void* d_out, int out_size) {
    const float* E   = (const float*)d_in[0];
    const int*   lab = (const int*)d_in[1];
    float*       out = (float*)d_out;

    triplet_k<<<N / A, T>>>(E, lab, out);
}

// round 15
// speedup vs baseline: 1.1099x; 1.1099x over previous
#include <cuda_runtime.h>
#include <cuda_bf16.h>

#define N 512
#define D 128
#define A 4
#define T 1024
#define GRID (N / A)    // 128
#define RS 520
#define NPOS_MAX 64
#define MARGIN 1.0f
#define EPSF 1e-8f

__device__ double       g_psum[GRID];
__device__ unsigned int g_pcnt[GRID];
__device__ unsigned int g_done;

__global__ __launch_bounds__(T, 1) void triplet_k(const float* __restrict__ E,
                                                  const int* __restrict__ lab,
                                                  float* __restrict__ out) {
    __shared__ float        s_ea[A * D];
    __shared__ float        s_row[A * RS];
    __shared__ float        s_prow[A * NPOS_MAX];
    __shared__ int          s_lab[N];
    __shared__ short        s_pos[A][NPOS_MAX];
    __shared__ int          s_np[A];
    __shared__ double       s_wsum[T / 32];
    __shared__ unsigned int s_wcnt[T / 32];
    __shared__ int          s_last;

    const int i0   = blockIdx.x * A;
    const int tid  = threadIdx.x;
    const int lane = tid & 31;
    const int w    = tid >> 5;            // 32 warps

    if (tid < A) s_np[tid] = 0;
    if (tid < A * D) s_ea[tid] = E[i0 * D + tid];
    if (tid < N)     s_lab[tid] = lab[tid];
    __syncthreads();

    // positives (threads 0..511, one j each)
    if (tid < N) {
        const int lj = s_lab[tid];
#pragma unroll
        for (int a = 0; a < A; a++) {
            if (tid != i0 + a && lj == s_lab[i0 + a]) {
                int p = atomicAdd(&s_np[a], 1);
                s_pos[a][p] = (short)tid;
            }
        }
    }

    // ---- dot phase (R10 proven pattern): warp w owns rows [16w,16w+16) ----
    {
        const int r = lane >> 3;
        const int s = lane & 7;
        const bool b1 = lane & 1;
        const bool b2 = lane & 2;
        const int base = (w << 4) + r;

        const float* ej0 = E + (base + 0) * D + s * 4;
        const float* ej1 = E + (base + 4) * D + s * 4;
        const float* ej2 = E + (base + 8) * D + s * 4;
        const float* ej3 = E + (base + 12) * D + s * 4;
        const float* ea  = s_ea + s * 4;

        float acc[4][4];
#pragma unroll
        for (int t = 0; t < 4; t++)
#pragma unroll
            for (int a = 0; a < 4; a++) acc[t][a] = 0.f;

#pragma unroll
        for (int q = 0; q < 4; q++) {
            const float4 a0 = *(const float4*)(ea + 0 * D + q * 32);
            const float4 a1 = *(const float4*)(ea + 1 * D + q * 32);
            const float4 a2 = *(const float4*)(ea + 2 * D + q * 32);
            const float4 a3 = *(const float4*)(ea + 3 * D + q * 32);
            const float4 v0 = *(const float4*)(ej0 + q * 32);
            const float4 v1 = *(const float4*)(ej1 + q * 32);
            const float4 v2 = *(const float4*)(ej2 + q * 32);
            const float4 v3 = *(const float4*)(ej3 + q * 32);

            acc[0][0] = fmaf(v0.x, a0.x, acc[0][0]); acc[0][0] = fmaf(v0.y, a0.y, acc[0][0]);
            acc[0][0] = fmaf(v0.z, a0.z, acc[0][0]); acc[0][0] = fmaf(v0.w, a0.w, acc[0][0]);
            acc[0][1] = fmaf(v0.x, a1.x, acc[0][1]); acc[0][1] = fmaf(v0.y, a1.y, acc[0][1]);
            acc[0][1] = fmaf(v0.z, a1.z, acc[0][1]); acc[0][1] = fmaf(v0.w, a1.w, acc[0][1]);
            acc[0][2] = fmaf(v0.x, a2.x, acc[0][2]); acc[0][2] = fmaf(v0.y, a2.y, acc[0][2]);
            acc[0][2] = fmaf(v0.z, a2.z, acc[0][2]); acc[0][2] = fmaf(v0.w, a2.w, acc[0][2]);
            acc[0][3] = fmaf(v0.x, a3.x, acc[0][3]); acc[0][3] = fmaf(v0.y, a3.y, acc[0][3]);
            acc[0][3] = fmaf(v0.z, a3.z, acc[0][3]); acc[0][3] = fmaf(v0.w, a3.w, acc[0][3]);

            acc[1][0] = fmaf(v1.x, a0.x, acc[1][0]); acc[1][0] = fmaf(v1.y, a0.y, acc[1][0]);
            acc[1][0] = fmaf(v1.z, a0.z, acc[1][0]); acc[1][0] = fmaf(v1.w, a0.w, acc[1][0]);
            acc[1][1] = fmaf(v1.x, a1.x, acc[1][1]); acc[1][1] = fmaf(v1.y, a1.y, acc[1][1]);
            acc[1][1] = fmaf(v1.z, a1.z, acc[1][1]); acc[1][1] = fmaf(v1.w, a1.w, acc[1][1]);
            acc[1][2] = fmaf(v1.x, a2.x, acc[1][2]); acc[1][2] = fmaf(v1.y, a2.y, acc[1][2]);
            acc[1][2] = fmaf(v1.z, a2.z, acc[1][2]); acc[1][2] = fmaf(v1.w, a2.w, acc[1][2]);
            acc[1][3] = fmaf(v1.x, a3.x, acc[1][3]); acc[1][3] = fmaf(v1.y, a3.y, acc[1][3]);
            acc[1][3] = fmaf(v1.z, a3.z, acc[1][3]); acc[1][3] = fmaf(v1.w, a3.w, acc[1][3]);

            acc[2][0] = fmaf(v2.x, a0.x, acc[2][0]); acc[2][0] = fmaf(v2.y, a0.y, acc[2][0]);
            acc[2][0] = fmaf(v2.z, a0.z, acc[2][0]); acc[2][0] = fmaf(v2.w, a0.w, acc[2][0]);
            acc[2][1] = fmaf(v2.x, a1.x, acc[2][1]); acc[2][1] = fmaf(v2.y, a1.y, acc[2][1]);
            acc[2][1] = fmaf(v2.z, a1.z, acc[2][1]); acc[2][1] = fmaf(v2.w, a1.w, acc[2][1]);
            acc[2][2] = fmaf(v2.x, a2.x, acc[2][2]); acc[2][2] = fmaf(v2.y, a2.y, acc[2][2]);
            acc[2][2] = fmaf(v2.z, a2.z, acc[2][2]); acc[2][2] = fmaf(v2.w, a2.w, acc[2][2]);
            acc[2][3] = fmaf(v2.x, a3.x, acc[2][3]); acc[2][3] = fmaf(v2.y, a3.y, acc[2][3]);
            acc[2][3] = fmaf(v2.z, a3.z, acc[2][3]); acc[2][3] = fmaf(v2.w, a3.w, acc[2][3]);

            acc[3][0] = fmaf(v3.x, a0.x, acc[3][0]); acc[3][0] = fmaf(v3.y, a0.y, acc[3][0]);
            acc[3][0] = fmaf(v3.z, a0.z, acc[3][0]); acc[3][0] = fmaf(v3.w, a0.w, acc[3][0]);
            acc[3][1] = fmaf(v3.x, a1.x, acc[3][1]); acc[3][1] = fmaf(v3.y, a1.y, acc[3][1]);
            acc[3][1] = fmaf(v3.z, a1.z, acc[3][1]); acc[3][1] = fmaf(v3.w, a1.w, acc[3][1]);
            acc[3][2] = fmaf(v3.x, a2.x, acc[3][2]); acc[3][2] = fmaf(v3.y, a2.y, acc[3][2]);
            acc[3][2] = fmaf(v3.z, a2.z, acc[3][2]); acc[3][2] = fmaf(v3.w, a2.w, acc[3][2]);
            acc[3][3] = fmaf(v3.x, a3.x, acc[3][3]); acc[3][3] = fmaf(v3.y, a3.y, acc[3][3]);
            acc[3][3] = fmaf(v3.z, a3.z, acc[3][3]); acc[3][3] = fmaf(v3.w, a3.w, acc[3][3]);
        }

#pragma unroll
        for (int t = 0; t < 4; t++) {
            const float c0 = acc[t][0], c1 = acc[t][1], c2 = acc[t][2], c3 = acc[t][3];
            float p01 = (b1 ? c1 : c0) + __shfl_xor_sync(0xffffffffu, b1 ? c0 : c1, 1);
            float p23 = (b1 ? c3 : c2) + __shfl_xor_sync(0xffffffffu, b1 ? c2 : c3, 1);
            float qv  = (b2 ? p23 : p01) + __shfl_xor_sync(0xffffffffu, b2 ? p01 : p23, 2);
            qv += __shfl_xor_sync(0xffffffffu, qv, 4);
            if ((lane & 4) == 0)
                s_row[(lane & 3) * RS + base + (t << 2)] = qv;
        }
    }
    __syncthreads();

    // ---- compact positive row values ----
    if (tid < A * NPOS_MAX) {
        const int a = tid >> 6;
        const int p = tid & 63;
        if (p < s_np[a]) s_prow[(a << 6) + p] = s_row[a * RS + s_pos[a][p]];
    }
    __syncthreads();

    // ---- hinge phase ----
    float lsum = 0.f;
    unsigned int lcnt = 0;
    {
        const int k    = tid & (N - 1);
        const int h    = tid >> 9;
        const int labk = s_lab[k];
        const float tv[A] = { MARGIN - s_row[0 * RS + k], MARGIN - s_row[1 * RS + k],
                              MARGIN - s_row[2 * RS + k], MARGIN - s_row[3 * RS + k] };

#pragma unroll
        for (int a = 0; a < A; a++) {
            if (labk != s_lab[i0 + a]) {
                const int    np = s_np[a];
                const float  ta = tv[a];
                const float* pr = s_prow + (a << 6);
                for (int p = h; p < np; p += 2) {
                    const float v = pr[p] + ta;
                    if (v > 0.f)  lsum += v;
                    if (v > EPSF) lcnt++;
                }
            }
        }
    }

    // ---- block reduction ----
    double dsum = (double)lsum;
#pragma unroll
    for (int o = 16; o > 0; o >>= 1) {
        dsum += __shfl_down_sync(0xffffffffu, dsum, o);
        lcnt += __shfl_down_sync(0xffffffffu, lcnt, o);
    }
    if (lane == 0) { s_wsum[w] = dsum; s_wcnt[w] = lcnt; }
    __syncthreads();

    // ---- epilogue: contention-free partials + single counter atomic ----
    if (tid == 0) {
        double t = 0.0;
        unsigned int c = 0;
#pragma unroll
        for (int ww = 0; ww < T / 32; ww++) { t += s_wsum[ww]; c += s_wcnt[ww]; }
        g_psum[blockIdx.x] = t;           // plain STG, no contention
        g_pcnt[blockIdx.x] = c;
        __threadfence();
        const unsigned int d = atomicAdd(&g_done, 1u);
        s_last = (d == GRID - 1);
    }
    __syncthreads();

    // ---- last CTA reduces the 128 partials (deterministic tree) ----
    if (s_last) {
        if (tid < GRID) {
            double t = g_psum[tid];
            unsigned int c = g_pcnt[tid];
#pragma unroll
            for (int o = 16; o > 0; o >>= 1) {
                t += __shfl_down_sync(0xffffffffu, t, o);
                c += __shfl_down_sync(0xffffffffu, c, o);
            }
            if (lane == 0) { s_wsum[w] = t; s_wcnt[w] = c; }
        }
        __syncthreads();
        if (tid == 0) {
            double t = 0.0;
            unsigned int c = 0;
#pragma unroll
            for (int ww = 0; ww < GRID / 32; ww++) { t += s_wsum[ww]; c += s_wcnt[ww]; }
            out[0] = (float)(t / ((double)c + (double)EPSF));
            atomicExch(&g_done, 0u);      // graph-replay reset
        }
    }
}

extern "C" void kernel_launch(void* const* d_in, const int* in_sizes, int n_in,
                              void* d_out, int out_size) {
    const float* E   = (const float*)d_in[0];
    const int*   lab = (const int*)d_in[1];
    float*       out = (float*)d_out;

    triplet_k<<<GRID, T>>>(E, lab, out);
}